// round 13
// baseline (speedup 1.0000x reference)
#include <cuda_runtime.h>
#include <cuda_fp16.h>
#include <cstdint>
#include <math.h>

#define NROWS 16384
#define H     768
#define KEXP  6912            // 768 inputs * 9 channels (silu + 8 bases)
#define BM    128
#define BN    128
#define BK    64
#define NKT   (KEXP / BK)     // 108
#define ROWB  128             // bytes per smem row (XOR-swizzled, no pad)
#define ASTGB (BM * ROWB)     // 16384 B
#define BSTGB (BN * ROWB)     // 16384 B
#define STGB  (ASTGB + BSTGB) // 32768 B per stage
#define NSTAGE 3
#define SMEMSZ (NSTAGE * STGB)   // 98304 B -> 2 CTAs/SM (192KB)
#define NTILE  (H / BN)       // 6
#define NSLICES 6             // one partial per row per n-tile CTA

// ---------------- device scratch (static; no allocation allowed) ----------
__device__ __align__(16) __half g_Aexp[(size_t)NROWS * KEXP];  // 226 MB
__device__ __align__(16) __half g_W1h[(size_t)H * KEXP];       // 10.6 MB
__device__ float2 g_W2c[H * 9];
__device__ __align__(16) float2 g_part[(size_t)NROWS * NSLICES]; // 0.8 MB

// ---------------- helpers ----------------
__device__ __forceinline__ float siluf(float x) { return x / (1.0f + __expf(-x)); }
__device__ __forceinline__ float geluf(float x) {
    return 0.5f * x * (1.0f + erff(x * 0.70710678118654752f));
}

// v[0] = silu(x); v[1..8] = cubic B-spline bases (knots -2.2 + 0.4j). Branchless.
__device__ __forceinline__ void expand9(float x, float v[9]) {
    v[0] = siluf(x);
    float t  = (x + 2.2f) * 2.5f;
    float kf = floorf(t);
    int   k  = (int)kf;
    float u  = t - kf, u2 = u * u, u3 = u2 * u, om = 1.0f - u;
    bool ok = (k >= 0) && (k <= 10);
    float b0 = om * om * om * (1.0f / 6.0f);
    float b1 = (4.0f - 6.0f * u2 + 3.0f * u3) * (1.0f / 6.0f);
    float b2 = (1.0f + 3.0f * u + 3.0f * u2 - 3.0f * u3) * (1.0f / 6.0f);
    float b3 = u3 * (1.0f / 6.0f);
    int j0 = k - 3;
#pragma unroll
    for (int j = 0; j < 8; j++) {
        int d = j - j0;
        float bv = (d == 0) ? b0 : (d == 1) ? b1 : (d == 2) ? b2 : (d == 3) ? b3 : 0.0f;
        v[1 + j] = ok ? bv : 0.0f;
    }
}

__device__ __forceinline__ uint32_t smem_u32(const void* p) {
    uint32_t a;
    asm("{ .reg .u64 t; cvta.to.shared.u64 t, %1; cvt.u32.u64 %0, t; }" : "=r"(a) : "l"(p));
    return a;
}

__device__ __forceinline__ void cp16(uint32_t dst, const __half* gsrc) {
    asm volatile("cp.async.cg.shared.global [%0], [%1], 16;" :: "r"(dst), "l"(gsrc) : "memory");
}
#define CP_COMMIT() asm volatile("cp.async.commit_group;" ::: "memory")
#define CP_WAIT1()  asm volatile("cp.async.wait_group 1;" ::: "memory")
#define CP_WAIT0()  asm volatile("cp.async.wait_group 0;" ::: "memory")

__device__ __forceinline__ void ldm_x4(unsigned* d, uint32_t addr) {
    asm volatile("ldmatrix.sync.aligned.m8n8.x4.shared.b16 {%0,%1,%2,%3}, [%4];"
                 : "=r"(d[0]), "=r"(d[1]), "=r"(d[2]), "=r"(d[3]) : "r"(addr));
}

__device__ __forceinline__ void mma_f16(float* c, const unsigned* a,
                                        unsigned b0, unsigned b1) {
    asm volatile(
        "mma.sync.aligned.m16n8k16.row.col.f32.f16.f16.f32 "
        "{%0,%1,%2,%3}, {%4,%5,%6,%7}, {%8,%9}, {%0,%1,%2,%3};\n"
        : "+f"(c[0]), "+f"(c[1]), "+f"(c[2]), "+f"(c[3])
        : "r"(a[0]), "r"(a[1]), "r"(a[2]), "r"(a[3]), "r"(b0), "r"(b1));
}

// ---------------- prep kernels (smem-staged, coalesced global writes) ------
__global__ void prep_w1h(const float* __restrict__ bw, const float* __restrict__ sw,
                         const float* __restrict__ sc) {
    __shared__ __half st[KEXP];                // 13824 B
    const int o = blockIdx.x;                  // one output row per block
    for (int i = threadIdx.x; i < H; i += 256) {
        int idx = o * H + i;
        float s = sc[idx];
        st[i * 9] = __float2half_rn(bw[idx]);
#pragma unroll
        for (int j = 0; j < 8; j++)
            st[i * 9 + 1 + j] = __float2half_rn(sw[(size_t)idx * 8 + j] * s);
    }
    __syncthreads();
    float4* dst = reinterpret_cast<float4*>(&g_W1h[(size_t)o * KEXP]);
    const float4* src = reinterpret_cast<const float4*>(st);
    for (int c = threadIdx.x; c < KEXP / 8; c += 256) dst[c] = src[c];
}

__global__ void prep_w2(const float* __restrict__ bw, const float* __restrict__ sw,
                        const float* __restrict__ sc) {
    int i = blockIdx.x * 256 + threadIdx.x;
    if (i >= H) return;
    float s0 = sc[i], s1 = sc[H + i];
    g_W2c[i * 9] = make_float2(bw[i], bw[H + i]);
#pragma unroll
    for (int j = 0; j < 8; j++)
        g_W2c[i * 9 + 1 + j] = make_float2(sw[(size_t)i * 8 + j] * s0,
                                           sw[(size_t)(H + i) * 8 + j] * s1);
}

// ---------------- one-time spline expansion (smem-staged, coalesced) -------
__global__ void expand_a(const float* __restrict__ x) {
    __shared__ __half st[KEXP];                // 13824 B
    const int row = blockIdx.x;                // one input row per block
    for (int i = threadIdx.x; i < H; i += 256) {
        float v[9];
        expand9(x[(size_t)row * H + i], v);
#pragma unroll
        for (int j = 0; j < 9; j++) st[i * 9 + j] = __float2half_rn(v[j]);
    }
    __syncthreads();
    float4* dst = reinterpret_cast<float4*>(&g_Aexp[(size_t)row * KEXP]);
    const float4* src = reinterpret_cast<const float4*>(st);
    for (int c = threadIdx.x; c < KEXP / 8; c += 256) dst[c] = src[c];
}

// ---------------- fused GEMM: layer1 + GELU + layer2-partials ----------------
__global__ void __launch_bounds__(256, 2) gemm_fused() {
    extern __shared__ __half sm[];
    const uint32_t sb = smem_u32(sm);
    const int tid = threadIdx.x, wid = tid >> 5, lane = tid & 31;
    const int g = lane >> 2, tg = lane & 3;
    const int wm = wid & 1, wn = wid >> 1;      // warp grid 2m x 4n, warp tile 64x32
    const int m0 = blockIdx.y * BM, n0 = blockIdx.x * BN;

    // ---- cp.async addressing: thread covers rows (tid>>3)+32r, 16B unit (tid&7) ----
    const int crow = tid >> 3, ccol = tid & 7;
    const int ckey = crow & 7;
    const __half* aBase = g_Aexp + (size_t)(m0 + crow) * KEXP + ccol * 8;
    const __half* bBase = g_W1h + (size_t)(n0 + crow) * KEXP + ccol * 8;
    const uint32_t aS = sb + crow * ROWB + (ccol ^ ckey) * 16;
    const uint32_t bS = aS + ASTGB;

    // ---- ldmatrix addressing: row base + precomputed swizzled 16B cols ----
    const int r8 = lane & 7, sel = lane >> 3;
    const uint32_t aRow = sb + (wm * 64 + ((sel & 1) << 3) + r8) * ROWB;
    const uint32_t bRow = sb + ASTGB + (wn * 32 + ((sel >> 1) << 3) + r8) * ROWB;
    uint32_t colA[4], colB[4];
#pragma unroll
    for (int ks = 0; ks < 4; ks++) {
        colA[ks] = ((((sel >> 1) + 2 * ks) ^ r8) << 4);
        colB[ks] = ((((sel & 1) + 2 * ks) ^ r8) << 4);
    }

    float c[4][4][4];
#pragma unroll
    for (int mt = 0; mt < 4; mt++)
#pragma unroll
        for (int nt = 0; nt < 4; nt++)
#pragma unroll
            for (int q = 0; q < 4; q++) c[mt][nt][q] = 0.0f;

    auto issue = [&](int kt) {
        const uint32_t st = (kt % NSTAGE) * STGB;
        const __half* ap = aBase + kt * BK;
#pragma unroll
        for (int r = 0; r < 4; r++)
            cp16(aS + st + r * (32 * ROWB), ap + (size_t)r * (32 * KEXP));
        const __half* bp = bBase + kt * BK;
#pragma unroll
        for (int r = 0; r < 4; r++)
            cp16(bS + st + r * (32 * ROWB), bp + (size_t)r * (32 * KEXP));
    };

    issue(0); CP_COMMIT();
    issue(1); CP_COMMIT();

    for (int kt = 0; kt < NKT; kt++) {
        if (kt < NKT - 2) { CP_WAIT1(); }   // stage kt complete, kt+1 in flight
        else              { CP_WAIT0(); }
        __syncthreads();                    // all warps done with iter kt-1 (slot (kt+2)%3 free)
        if (kt + 2 < NKT) { issue(kt + 2); CP_COMMIT(); }

        const uint32_t aR = aRow + (kt % NSTAGE) * STGB;
        const uint32_t bR = bRow + (kt % NSTAGE) * STGB;
#pragma unroll
        for (int ks = 0; ks < 4; ks++) {
            unsigned a[4][4], b[2][4];
#pragma unroll
            for (int mt = 0; mt < 4; mt++)
                ldm_x4(a[mt], aR + mt * (16 * ROWB) + colA[ks]);
#pragma unroll
            for (int np = 0; np < 2; np++)
                ldm_x4(b[np], bR + np * (16 * ROWB) + colB[ks]);
#pragma unroll
            for (int nt = 0; nt < 4; nt++) {
                unsigned b0 = b[nt >> 1][(nt & 1) * 2];
                unsigned b1 = b[nt >> 1][(nt & 1) * 2 + 1];
#pragma unroll
                for (int mt = 0; mt < 4; mt++)
                    mma_f16(c[mt][nt], a[mt], b0, b1);
            }
        }
    }

    // epilogue: gelu + spline-expand + layer-2 partial dot, then intra-CTA reduce
    __syncthreads();                        // mainloop smem reads complete before reuse
    float2* red = reinterpret_cast<float2*>(sm);   // [16][128] float2 = 16KB (aliases stage 0)
    const int sl16 = wn * 4 + tg;
#pragma unroll
    for (int mt = 0; mt < 4; mt++) {
#pragma unroll
        for (int hq = 0; hq < 2; hq++) {
            int rl = wm * 64 + mt * 16 + g + hq * 8;   // local row 0..127
            float p0 = 0.0f, p1 = 0.0f;
#pragma unroll
            for (int nt = 0; nt < 4; nt++) {
#pragma unroll
                for (int par = 0; par < 2; par++) {
                    float y = geluf(c[mt][nt][hq * 2 + par]);
                    int col = n0 + wn * 32 + nt * 8 + 2 * tg + par;
                    float v[9];
                    expand9(y, v);
                    const float2* w = &g_W2c[col * 9];
#pragma unroll
                    for (int j = 0; j < 9; j++) {
                        float2 wj = __ldg(&w[j]);
                        p0 = fmaf(v[j], wj.x, p0);
                        p1 = fmaf(v[j], wj.y, p1);
                    }
                }
            }
            red[sl16 * 128 + rl] = make_float2(p0, p1);
        }
    }
    __syncthreads();
    if (tid < 128) {
        float a = 0.0f, b = 0.0f;
#pragma unroll
        for (int s = 0; s < 16; s++) {
            float2 v = red[s * 128 + tid];
            a += v.x; b += v.y;
        }
        g_part[(size_t)(m0 + tid) * NSLICES + blockIdx.x] = make_float2(a, b);
    }
}

// ---------------- final reduce (6 float2 per row) ----------------
__global__ void reduce2(float* __restrict__ out) {
    int row = blockIdx.x * 256 + threadIdx.x;
    if (row >= NROWS) return;
    const float4* p = reinterpret_cast<const float4*>(&g_part[(size_t)row * NSLICES]);
    float a = 0.0f, b = 0.0f;
#pragma unroll
    for (int s = 0; s < NSLICES / 2; s++) {
        float4 v = p[s];
        a += v.x + v.z;
        b += v.y + v.w;
    }
    out[row * 2 + 0] = a;
    out[row * 2 + 1] = b;
}

// ---------------------------------------------------------------------------
extern "C" void kernel_launch(void* const* d_in, const int* in_sizes, int n_in,
                              void* d_out, int out_size) {
    const float* hidden = (const float*)d_in[0];
    const float* bw1 = (const float*)d_in[1];
    const float* sw1 = (const float*)d_in[2];
    const float* sc1 = (const float*)d_in[3];
    const float* bw2 = (const float*)d_in[4];
    const float* sw2 = (const float*)d_in[5];
    const float* sc2 = (const float*)d_in[6];
    float* out = (float*)d_out;

    cudaFuncSetAttribute(gemm_fused, cudaFuncAttributeMaxDynamicSharedMemorySize, SMEMSZ);

    prep_w1h<<<H, 256>>>(bw1, sw1, sc1);
    prep_w2<<<(H + 255) / 256, 256>>>(bw2, sw2, sc2);
    expand_a<<<NROWS, 256>>>(hidden);
    gemm_fused<<<dim3(NTILE, NROWS / BM), 256, SMEMSZ>>>();
    reduce2<<<NROWS / 256, 256>>>(out);
}

// round 14
// speedup vs baseline: 1.0440x; 1.0440x over previous
#include <cuda_runtime.h>
#include <cuda_fp16.h>
#include <cstdint>
#include <math.h>

#define NROWS 16384
#define H     768
#define KEXP  6912            // 768 inputs * 9 channels (silu + 8 bases)
#define BM    128
#define BN    128
#define BK    64
#define NKT   (KEXP / BK)     // 108
#define ROWB  128             // bytes per smem row (XOR-swizzled, no pad)
#define ASTGB (BM * ROWB)     // 16384 B
#define BSTGB (BN * ROWB)     // 16384 B
#define STGB  (ASTGB + BSTGB) // 32768 B per stage
#define NSTAGE 3
#define SMEMSZ (NSTAGE * STGB)   // 98304 B -> 2 CTAs/SM (192KB, 32 warps/SM)
#define NTILE  (H / BN)       // 6
#define NSLICES 6             // one partial per row per n-tile CTA
#define NT    512             // threads per CTA (16 warps)

// ---------------- device scratch (static; no allocation allowed) ----------
__device__ __align__(16) __half g_Aexp[(size_t)NROWS * KEXP];  // 226 MB
__device__ __align__(16) __half g_W1h[(size_t)H * KEXP];       // 10.6 MB
__device__ float2 g_W2c[H * 9];
__device__ __align__(16) float2 g_part[(size_t)NROWS * NSLICES]; // 0.8 MB

// ---------------- helpers ----------------
__device__ __forceinline__ float siluf(float x) { return x / (1.0f + __expf(-x)); }
__device__ __forceinline__ float geluf(float x) {
    return 0.5f * x * (1.0f + erff(x * 0.70710678118654752f));
}

// v[0] = silu(x); v[1..8] = cubic B-spline bases (knots -2.2 + 0.4j). Branchless.
__device__ __forceinline__ void expand9(float x, float v[9]) {
    v[0] = siluf(x);
    float t  = (x + 2.2f) * 2.5f;
    float kf = floorf(t);
    int   k  = (int)kf;
    float u  = t - kf, u2 = u * u, u3 = u2 * u, om = 1.0f - u;
    bool ok = (k >= 0) && (k <= 10);
    float b0 = om * om * om * (1.0f / 6.0f);
    float b1 = (4.0f - 6.0f * u2 + 3.0f * u3) * (1.0f / 6.0f);
    float b2 = (1.0f + 3.0f * u + 3.0f * u2 - 3.0f * u3) * (1.0f / 6.0f);
    float b3 = u3 * (1.0f / 6.0f);
    int j0 = k - 3;
#pragma unroll
    for (int j = 0; j < 8; j++) {
        int d = j - j0;
        float bv = (d == 0) ? b0 : (d == 1) ? b1 : (d == 2) ? b2 : (d == 3) ? b3 : 0.0f;
        v[1 + j] = ok ? bv : 0.0f;
    }
}

__device__ __forceinline__ uint32_t smem_u32(const void* p) {
    uint32_t a;
    asm("{ .reg .u64 t; cvta.to.shared.u64 t, %1; cvt.u32.u64 %0, t; }" : "=r"(a) : "l"(p));
    return a;
}

__device__ __forceinline__ void cp16(uint32_t dst, const __half* gsrc) {
    asm volatile("cp.async.cg.shared.global [%0], [%1], 16;" :: "r"(dst), "l"(gsrc) : "memory");
}
#define CP_COMMIT() asm volatile("cp.async.commit_group;" ::: "memory")
#define CP_WAIT1()  asm volatile("cp.async.wait_group 1;" ::: "memory")
#define CP_WAIT0()  asm volatile("cp.async.wait_group 0;" ::: "memory")

__device__ __forceinline__ void ldm_x4(unsigned* d, uint32_t addr) {
    asm volatile("ldmatrix.sync.aligned.m8n8.x4.shared.b16 {%0,%1,%2,%3}, [%4];"
                 : "=r"(d[0]), "=r"(d[1]), "=r"(d[2]), "=r"(d[3]) : "r"(addr));
}

__device__ __forceinline__ void mma_f16(float* c, const unsigned* a,
                                        unsigned b0, unsigned b1) {
    asm volatile(
        "mma.sync.aligned.m16n8k16.row.col.f32.f16.f16.f32 "
        "{%0,%1,%2,%3}, {%4,%5,%6,%7}, {%8,%9}, {%0,%1,%2,%3};\n"
        : "+f"(c[0]), "+f"(c[1]), "+f"(c[2]), "+f"(c[3])
        : "r"(a[0]), "r"(a[1]), "r"(a[2]), "r"(a[3]), "r"(b0), "r"(b1));
}

// ---------------- prep kernels (smem-staged, coalesced global writes) ------
__global__ void prep_w1h(const float* __restrict__ bw, const float* __restrict__ sw,
                         const float* __restrict__ sc) {
    __shared__ __half st[KEXP];                // 13824 B
    const int o = blockIdx.x;                  // one output row per block
    for (int i = threadIdx.x; i < H; i += 256) {
        int idx = o * H + i;
        float s = sc[idx];
        st[i * 9] = __float2half_rn(bw[idx]);
#pragma unroll
        for (int j = 0; j < 8; j++)
            st[i * 9 + 1 + j] = __float2half_rn(sw[(size_t)idx * 8 + j] * s);
    }
    __syncthreads();
    float4* dst = reinterpret_cast<float4*>(&g_W1h[(size_t)o * KEXP]);
    const float4* src = reinterpret_cast<const float4*>(st);
    for (int c = threadIdx.x; c < KEXP / 8; c += 256) dst[c] = src[c];
}

__global__ void prep_w2(const float* __restrict__ bw, const float* __restrict__ sw,
                        const float* __restrict__ sc) {
    int i = blockIdx.x * 256 + threadIdx.x;
    if (i >= H) return;
    float s0 = sc[i], s1 = sc[H + i];
    g_W2c[i * 9] = make_float2(bw[i], bw[H + i]);
#pragma unroll
    for (int j = 0; j < 8; j++)
        g_W2c[i * 9 + 1 + j] = make_float2(sw[(size_t)i * 8 + j] * s0,
                                           sw[(size_t)(H + i) * 8 + j] * s1);
}

// ---------------- one-time spline expansion (smem-staged, coalesced) -------
__global__ void expand_a(const float* __restrict__ x) {
    __shared__ __half st[KEXP];                // 13824 B
    const int row = blockIdx.x;                // one input row per block
    for (int i = threadIdx.x; i < H; i += 256) {
        float v[9];
        expand9(x[(size_t)row * H + i], v);
#pragma unroll
        for (int j = 0; j < 9; j++) st[i * 9 + j] = __float2half_rn(v[j]);
    }
    __syncthreads();
    float4* dst = reinterpret_cast<float4*>(&g_Aexp[(size_t)row * KEXP]);
    const float4* src = reinterpret_cast<const float4*>(st);
    for (int c = threadIdx.x; c < KEXP / 8; c += 256) dst[c] = src[c];
}

// ---------------- fused GEMM: layer1 + GELU + layer2-partials ----------------
__global__ void __launch_bounds__(NT, 2) gemm_fused() {
    extern __shared__ __half sm[];
    const uint32_t sb = smem_u32(sm);
    const int tid = threadIdx.x, wid = tid >> 5, lane = tid & 31;
    const int g = lane >> 2, tg = lane & 3;
    const int wm = wid & 3, wn = wid >> 2;      // warp grid 4m x 4n, warp tile 32x32
    const int m0 = blockIdx.y * BM, n0 = blockIdx.x * BN;

    // ---- cp.async addressing: thread covers rows (tid>>3)+64r, 16B unit (tid&7) ----
    const int crow = tid >> 3, ccol = tid & 7;  // crow 0..63
    const int ckey = crow & 7;                  // invariant under +64r
    const __half* aBase = g_Aexp + (size_t)(m0 + crow) * KEXP + ccol * 8;
    const __half* bBase = g_W1h + (size_t)(n0 + crow) * KEXP + ccol * 8;
    const uint32_t aS = sb + crow * ROWB + (ccol ^ ckey) * 16;
    const uint32_t bS = aS + ASTGB;

    // ---- ldmatrix addressing: row base + precomputed swizzled 16B cols ----
    const int r8 = lane & 7, sel = lane >> 3;
    const uint32_t aRow = sb + (wm * 32 + ((sel & 1) << 3) + r8) * ROWB;
    const uint32_t bRow = sb + ASTGB + (wn * 32 + ((sel >> 1) << 3) + r8) * ROWB;
    uint32_t colA[4], colB[4];
#pragma unroll
    for (int ks = 0; ks < 4; ks++) {
        colA[ks] = ((((sel >> 1) + 2 * ks) ^ r8) << 4);
        colB[ks] = ((((sel & 1) + 2 * ks) ^ r8) << 4);
    }

    float c[2][4][4];
#pragma unroll
    for (int mt = 0; mt < 2; mt++)
#pragma unroll
        for (int nt = 0; nt < 4; nt++)
#pragma unroll
            for (int q = 0; q < 4; q++) c[mt][nt][q] = 0.0f;

    auto issue = [&](int kt) {
        const uint32_t st = (kt % NSTAGE) * STGB;
        const __half* ap = aBase + kt * BK;
#pragma unroll
        for (int r = 0; r < 2; r++)
            cp16(aS + st + r * (64 * ROWB), ap + (size_t)r * (64 * KEXP));
        const __half* bp = bBase + kt * BK;
#pragma unroll
        for (int r = 0; r < 2; r++)
            cp16(bS + st + r * (64 * ROWB), bp + (size_t)r * (64 * KEXP));
    };

    issue(0); CP_COMMIT();
    issue(1); CP_COMMIT();

    for (int kt = 0; kt < NKT; kt++) {
        if (kt < NKT - 2) { CP_WAIT1(); }   // stage kt complete, kt+1 in flight
        else              { CP_WAIT0(); }
        __syncthreads();                    // all warps done with iter kt-1 (slot (kt+2)%3 free)
        if (kt + 2 < NKT) { issue(kt + 2); CP_COMMIT(); }

        const uint32_t aR = aRow + (kt % NSTAGE) * STGB;
        const uint32_t bR = bRow + (kt % NSTAGE) * STGB;
#pragma unroll
        for (int ks = 0; ks < 4; ks++) {
            unsigned a[2][4], b[2][4];
#pragma unroll
            for (int mt = 0; mt < 2; mt++)
                ldm_x4(a[mt], aR + mt * (16 * ROWB) + colA[ks]);
#pragma unroll
            for (int np = 0; np < 2; np++)
                ldm_x4(b[np], bR + np * (16 * ROWB) + colB[ks]);
#pragma unroll
            for (int nt = 0; nt < 4; nt++) {
                unsigned b0 = b[nt >> 1][(nt & 1) * 2];
                unsigned b1 = b[nt >> 1][(nt & 1) * 2 + 1];
#pragma unroll
                for (int mt = 0; mt < 2; mt++)
                    mma_f16(c[mt][nt], a[mt], b0, b1);
            }
        }
    }

    // epilogue: gelu + spline-expand + layer-2 partial dot, then intra-CTA reduce
    __syncthreads();                        // mainloop smem reads complete before reuse
    float2* red = reinterpret_cast<float2*>(sm);   // [16][128] float2 = 16KB (aliases stage 0)
    const int sl16 = wn * 4 + tg;
#pragma unroll
    for (int mt = 0; mt < 2; mt++) {
#pragma unroll
        for (int hq = 0; hq < 2; hq++) {
            int rl = wm * 32 + mt * 16 + g + hq * 8;   // local row 0..127
            float p0 = 0.0f, p1 = 0.0f;
#pragma unroll
            for (int nt = 0; nt < 4; nt++) {
#pragma unroll
                for (int par = 0; par < 2; par++) {
                    float y = geluf(c[mt][nt][hq * 2 + par]);
                    int col = n0 + wn * 32 + nt * 8 + 2 * tg + par;
                    float v[9];
                    expand9(y, v);
                    const float2* w = &g_W2c[col * 9];
#pragma unroll
                    for (int j = 0; j < 9; j++) {
                        float2 wj = __ldg(&w[j]);
                        p0 = fmaf(v[j], wj.x, p0);
                        p1 = fmaf(v[j], wj.y, p1);
                    }
                }
            }
            red[sl16 * 128 + rl] = make_float2(p0, p1);
        }
    }
    __syncthreads();
    if (tid < 128) {
        float a = 0.0f, b = 0.0f;
#pragma unroll
        for (int s = 0; s < 16; s++) {
            float2 v = red[s * 128 + tid];
            a += v.x; b += v.y;
        }
        g_part[(size_t)(m0 + tid) * NSLICES + blockIdx.x] = make_float2(a, b);
    }
}

// ---------------- final reduce (6 float2 per row) ----------------
__global__ void reduce2(float* __restrict__ out) {
    int row = blockIdx.x * 256 + threadIdx.x;
    if (row >= NROWS) return;
    const float4* p = reinterpret_cast<const float4*>(&g_part[(size_t)row * NSLICES]);
    float a = 0.0f, b = 0.0f;
#pragma unroll
    for (int s = 0; s < NSLICES / 2; s++) {
        float4 v = p[s];
        a += v.x + v.z;
        b += v.y + v.w;
    }
    out[row * 2 + 0] = a;
    out[row * 2 + 1] = b;
}

// ---------------------------------------------------------------------------
extern "C" void kernel_launch(void* const* d_in, const int* in_sizes, int n_in,
                              void* d_out, int out_size) {
    const float* hidden = (const float*)d_in[0];
    const float* bw1 = (const float*)d_in[1];
    const float* sw1 = (const float*)d_in[2];
    const float* sc1 = (const float*)d_in[3];
    const float* bw2 = (const float*)d_in[4];
    const float* sw2 = (const float*)d_in[5];
    const float* sc2 = (const float*)d_in[6];
    float* out = (float*)d_out;

    cudaFuncSetAttribute(gemm_fused, cudaFuncAttributeMaxDynamicSharedMemorySize, SMEMSZ);

    prep_w1h<<<H, 256>>>(bw1, sw1, sc1);
    prep_w2<<<(H + 255) / 256, 256>>>(bw2, sw2, sc2);
    expand_a<<<NROWS, 256>>>(hidden);
    gemm_fused<<<dim3(NTILE, NROWS / BM), NT, SMEMSZ>>>();
    reduce2<<<NROWS / 256, 256>>>(out);
}

// round 16
// speedup vs baseline: 1.1946x; 1.1443x over previous
#include <cuda_runtime.h>
#include <cuda_fp16.h>
#include <cstdint>
#include <math.h>

#define NROWS 16384
#define H     768
#define KEXP  6912            // 768 inputs * 9 channels (silu + 8 bases)
#define BM    128
#define BN    64
#define BK    64
#define NKT   (KEXP / BK)     // 108
#define ROWB  128             // bytes per smem row (XOR-swizzled, no pad)
#define ASTGB (BM * ROWB)     // 16384 B
#define BSTGB (BN * ROWB)     // 8192 B
#define STGB  (ASTGB + BSTGB) // 24576 B per stage
#define NSTAGE 3
#define SMEMSZ (NSTAGE * STGB)   // 73728 B -> 3 CTAs/SM (216KB)
#define NTILE  (H / BN)       // 12
#define NSLICES 12            // one partial per row per n-tile CTA

// ---------------- device scratch (static; no allocation allowed) ----------
__device__ __align__(16) __half g_Aexp[(size_t)NROWS * KEXP];  // 226 MB
__device__ __align__(16) __half g_W1h[(size_t)H * KEXP];       // 10.6 MB
__device__ float2 g_W2c[H * 9];
__device__ __align__(16) float2 g_part[(size_t)NROWS * NSLICES]; // 1.6 MB

// ---------------- helpers ----------------
__device__ __forceinline__ float siluf(float x) { return x / (1.0f + __expf(-x)); }
__device__ __forceinline__ float geluf(float x) {
    return 0.5f * x * (1.0f + erff(x * 0.70710678118654752f));
}

// v[0] = silu(x); v[1..8] = cubic B-spline bases (knots -2.2 + 0.4j). Branchless.
__device__ __forceinline__ void expand9(float x, float v[9]) {
    v[0] = siluf(x);
    float t  = (x + 2.2f) * 2.5f;
    float kf = floorf(t);
    int   k  = (int)kf;
    float u  = t - kf, u2 = u * u, u3 = u2 * u, om = 1.0f - u;
    bool ok = (k >= 0) && (k <= 10);
    float b0 = om * om * om * (1.0f / 6.0f);
    float b1 = (4.0f - 6.0f * u2 + 3.0f * u3) * (1.0f / 6.0f);
    float b2 = (1.0f + 3.0f * u + 3.0f * u2 - 3.0f * u3) * (1.0f / 6.0f);
    float b3 = u3 * (1.0f / 6.0f);
    int j0 = k - 3;
#pragma unroll
    for (int j = 0; j < 8; j++) {
        int d = j - j0;
        float bv = (d == 0) ? b0 : (d == 1) ? b1 : (d == 2) ? b2 : (d == 3) ? b3 : 0.0f;
        v[1 + j] = ok ? bv : 0.0f;
    }
}

__device__ __forceinline__ uint32_t smem_u32(const void* p) {
    uint32_t a;
    asm("{ .reg .u64 t; cvta.to.shared.u64 t, %1; cvt.u32.u64 %0, t; }" : "=r"(a) : "l"(p));
    return a;
}

__device__ __forceinline__ void cp16(uint32_t dst, const __half* gsrc) {
    asm volatile("cp.async.cg.shared.global [%0], [%1], 16;" :: "r"(dst), "l"(gsrc) : "memory");
}
#define CP_COMMIT() asm volatile("cp.async.commit_group;" ::: "memory")
#define CP_WAIT1()  asm volatile("cp.async.wait_group 1;" ::: "memory")
#define CP_WAIT0()  asm volatile("cp.async.wait_group 0;" ::: "memory")

__device__ __forceinline__ void ldm_x4(unsigned* d, uint32_t addr) {
    asm volatile("ldmatrix.sync.aligned.m8n8.x4.shared.b16 {%0,%1,%2,%3}, [%4];"
                 : "=r"(d[0]), "=r"(d[1]), "=r"(d[2]), "=r"(d[3]) : "r"(addr));
}

__device__ __forceinline__ void mma_f16(float* c, const unsigned* a,
                                        unsigned b0, unsigned b1) {
    asm volatile(
        "mma.sync.aligned.m16n8k16.row.col.f32.f16.f16.f32 "
        "{%0,%1,%2,%3}, {%4,%5,%6,%7}, {%8,%9}, {%0,%1,%2,%3};\n"
        : "+f"(c[0]), "+f"(c[1]), "+f"(c[2]), "+f"(c[3])
        : "r"(a[0]), "r"(a[1]), "r"(a[2]), "r"(a[3]), "r"(b0), "r"(b1));
}

// ---------------- merged weight prep (w1 rows + w2 in one launch) ----------
__global__ void prep_w(const float* __restrict__ bw1, const float* __restrict__ sw1,
                       const float* __restrict__ sc1, const float* __restrict__ bw2,
                       const float* __restrict__ sw2, const float* __restrict__ sc2) {
    __shared__ __half st[KEXP];                // 13824 B
    const int o = blockIdx.x;
    if (o < H) {                               // layer-1 weight row o
        for (int i = threadIdx.x; i < H; i += 256) {
            int idx = o * H + i;
            float s = sc1[idx];
            st[i * 9] = __float2half_rn(bw1[idx]);
#pragma unroll
            for (int j = 0; j < 8; j++)
                st[i * 9 + 1 + j] = __float2half_rn(sw1[(size_t)idx * 8 + j] * s);
        }
        __syncthreads();
        float4* dst = reinterpret_cast<float4*>(&g_W1h[(size_t)o * KEXP]);
        const float4* src = reinterpret_cast<const float4*>(st);
        for (int c = threadIdx.x; c < KEXP / 8; c += 256) dst[c] = src[c];
    } else {                                   // layer-2 combined weights
        for (int i = threadIdx.x; i < H; i += 256) {
            float s0 = sc2[i], s1 = sc2[H + i];
            g_W2c[i * 9] = make_float2(bw2[i], bw2[H + i]);
#pragma unroll
            for (int j = 0; j < 8; j++)
                g_W2c[i * 9 + 1 + j] = make_float2(sw2[(size_t)i * 8 + j] * s0,
                                                   sw2[(size_t)(H + i) * 8 + j] * s1);
        }
    }
}

// ---------------- one-time spline expansion (2 rows/block, coalesced) ------
__global__ void expand_a(const float* __restrict__ x) {
    __shared__ __half st[2 * KEXP];            // 27648 B
    const int half = threadIdx.x >> 8;         // 0/1 -> which row
    const int t    = threadIdx.x & 255;
    const int row  = blockIdx.x * 2 + half;
    __half* strow = st + half * KEXP;
    for (int i = t; i < H; i += 256) {
        float v[9];
        expand9(x[(size_t)row * H + i], v);
#pragma unroll
        for (int j = 0; j < 9; j++) strow[i * 9 + j] = __float2half_rn(v[j]);
    }
    __syncthreads();
    float4* dst = reinterpret_cast<float4*>(&g_Aexp[(size_t)(blockIdx.x * 2) * KEXP]);
    const float4* src = reinterpret_cast<const float4*>(st);
    for (int c = threadIdx.x; c < 2 * KEXP / 8; c += 512) dst[c] = src[c];
}

// ---------------- fused GEMM: layer1 + GELU + layer2-partials (r12 exact) --
__global__ void __launch_bounds__(256, 3) gemm_fused() {
    extern __shared__ __half sm[];
    const uint32_t sb = smem_u32(sm);
    const int tid = threadIdx.x, wid = tid >> 5, lane = tid & 31;
    const int g = lane >> 2, tg = lane & 3;
    const int wm = wid & 3, wn = wid >> 2;      // warp grid 4m x 2n, warp tile 32x32
    const int m0 = blockIdx.y * BM, n0 = blockIdx.x * BN;

    // ---- cp.async addressing: thread covers rows (tid>>3)+32r, 16B unit (tid&7) ----
    const int crow = tid >> 3, ccol = tid & 7;
    const int ckey = crow & 7;
    const __half* aBase = g_Aexp + (size_t)(m0 + crow) * KEXP + ccol * 8;
    const __half* bBase = g_W1h + (size_t)(n0 + crow) * KEXP + ccol * 8;
    const uint32_t aS = sb + crow * ROWB + (ccol ^ ckey) * 16;
    const uint32_t bS = aS + ASTGB;

    // ---- ldmatrix addressing: row base + precomputed swizzled 16B cols ----
    const int r8 = lane & 7, sel = lane >> 3;
    const uint32_t aRow = sb + (wm * 32 + ((sel & 1) << 3) + r8) * ROWB;
    const uint32_t bRow = sb + ASTGB + (wn * 32 + ((sel >> 1) << 3) + r8) * ROWB;
    uint32_t colA[4], colB[4];
#pragma unroll
    for (int ks = 0; ks < 4; ks++) {
        colA[ks] = ((((sel >> 1) + 2 * ks) ^ r8) << 4);
        colB[ks] = ((((sel & 1) + 2 * ks) ^ r8) << 4);
    }

    float c[2][4][4];
#pragma unroll
    for (int mt = 0; mt < 2; mt++)
#pragma unroll
        for (int nt = 0; nt < 4; nt++)
#pragma unroll
            for (int q = 0; q < 4; q++) c[mt][nt][q] = 0.0f;

    auto issue = [&](int kt) {
        const uint32_t st = (kt % NSTAGE) * STGB;
        const __half* ap = aBase + kt * BK;
#pragma unroll
        for (int r = 0; r < 4; r++)
            cp16(aS + st + r * (32 * ROWB), ap + (size_t)r * (32 * KEXP));
        const __half* bp = bBase + kt * BK;
#pragma unroll
        for (int r = 0; r < 2; r++)
            cp16(bS + st + r * (32 * ROWB), bp + (size_t)r * (32 * KEXP));
    };

    issue(0); CP_COMMIT();
    issue(1); CP_COMMIT();

    for (int kt = 0; kt < NKT; kt++) {
        if (kt < NKT - 2) { CP_WAIT1(); }   // stage kt complete, kt+1 in flight
        else              { CP_WAIT0(); }
        __syncthreads();                    // all warps done with iter kt-1 (slot (kt+2)%3 free)
        if (kt + 2 < NKT) { issue(kt + 2); CP_COMMIT(); }

        const uint32_t aR = aRow + (kt % NSTAGE) * STGB;
        const uint32_t bR = bRow + (kt % NSTAGE) * STGB;
#pragma unroll
        for (int ks = 0; ks < 4; ks++) {
            unsigned a[2][4], b[2][4];
#pragma unroll
            for (int mt = 0; mt < 2; mt++)
                ldm_x4(a[mt], aR + mt * (16 * ROWB) + colA[ks]);
#pragma unroll
            for (int np = 0; np < 2; np++)
                ldm_x4(b[np], bR + np * (16 * ROWB) + colB[ks]);
#pragma unroll
            for (int nt = 0; nt < 4; nt++) {
                unsigned b0 = b[nt >> 1][(nt & 1) * 2];
                unsigned b1 = b[nt >> 1][(nt & 1) * 2 + 1];
#pragma unroll
                for (int mt = 0; mt < 2; mt++)
                    mma_f16(c[mt][nt], a[mt], b0, b1);
            }
        }
    }

    // epilogue: gelu + spline-expand + layer-2 partial dot, then intra-CTA reduce
    __syncthreads();                        // mainloop smem reads complete before reuse
    float2* red = reinterpret_cast<float2*>(sm);   // [8][128] float2 = 8KB (aliases stage 0)
    const int sl8 = wn * 4 + tg;
#pragma unroll
    for (int mt = 0; mt < 2; mt++) {
#pragma unroll
        for (int hq = 0; hq < 2; hq++) {
            int rl = wm * 32 + mt * 16 + g + hq * 8;   // local row 0..127
            float p0 = 0.0f, p1 = 0.0f;
#pragma unroll
            for (int nt = 0; nt < 4; nt++) {
#pragma unroll
                for (int par = 0; par < 2; par++) {
                    float y = geluf(c[mt][nt][hq * 2 + par]);
                    int col = n0 + wn * 32 + nt * 8 + 2 * tg + par;
                    float v[9];
                    expand9(y, v);
                    const float2* w = &g_W2c[col * 9];
#pragma unroll
                    for (int j = 0; j < 9; j++) {
                        float2 wj = __ldg(&w[j]);
                        p0 = fmaf(v[j], wj.x, p0);
                        p1 = fmaf(v[j], wj.y, p1);
                    }
                }
            }
            red[sl8 * 128 + rl] = make_float2(p0, p1);
        }
    }
    __syncthreads();
    if (tid < 128) {
        float a = 0.0f, b = 0.0f;
#pragma unroll
        for (int s = 0; s < 8; s++) {
            float2 v = red[s * 128 + tid];
            a += v.x; b += v.y;
        }
        g_part[(size_t)(m0 + tid) * NSLICES + blockIdx.x] = make_float2(a, b);
    }
}

// ---------------- final reduce (12 float2 per row) ----------------
__global__ void reduce2(float* __restrict__ out) {
    int row = blockIdx.x * 256 + threadIdx.x;
    if (row >= NROWS) return;
    const float4* p = reinterpret_cast<const float4*>(&g_part[(size_t)row * NSLICES]);
    float a = 0.0f, b = 0.0f;
#pragma unroll
    for (int s = 0; s < NSLICES / 2; s++) {
        float4 v = p[s];
        a += v.x + v.z;
        b += v.y + v.w;
    }
    out[row * 2 + 0] = a;
    out[row * 2 + 1] = b;
}

// ---------------------------------------------------------------------------
extern "C" void kernel_launch(void* const* d_in, const int* in_sizes, int n_in,
                              void* d_out, int out_size) {
    const float* hidden = (const float*)d_in[0];
    const float* bw1 = (const float*)d_in[1];
    const float* sw1 = (const float*)d_in[2];
    const float* sc1 = (const float*)d_in[3];
    const float* bw2 = (const float*)d_in[4];
    const float* sw2 = (const float*)d_in[5];
    const float* sc2 = (const float*)d_in[6];
    float* out = (float*)d_out;

    cudaFuncSetAttribute(gemm_fused, cudaFuncAttributeMaxDynamicSharedMemorySize, SMEMSZ);

    prep_w<<<H + 1, 256>>>(bw1, sw1, sc1, bw2, sw2, sc2);
    expand_a<<<NROWS / 2, 512>>>(hidden);
    gemm_fused<<<dim3(NTILE, NROWS / BM), 256, SMEMSZ>>>();
    reduce2<<<NROWS / 256, 256>>>(out);
}

// round 17
// speedup vs baseline: 1.1960x; 1.0012x over previous
#include <cuda_runtime.h>
#include <cuda_fp16.h>
#include <cstdint>
#include <math.h>

#define NROWS 16384
#define H     768
#define KEXP  6912            // 768 inputs * 9 channels (silu + 8 bases)
#define BM    128
#define BN    64
#define BK    64
#define NKT   (KEXP / BK)     // 108
#define ROWB  128             // bytes per smem row (XOR-swizzled, no pad)
#define ASTGB (BM * ROWB)     // 16384 B
#define BSTGB (BN * ROWB)     // 8192 B
#define STGB  (ASTGB + BSTGB) // 24576 B per stage
#define NSTAGE 3
#define SMEMSZ (NSTAGE * STGB)   // 73728 B -> 3 CTAs/SM (216KB)
#define NTILE  (H / BN)       // 12
#define NSLICES 12            // one partial per row per n-tile CTA

// ---------------- device scratch (static; no allocation allowed) ----------
__device__ __align__(16) __half g_Aexp[(size_t)NROWS * KEXP];  // 226 MB
__device__ __align__(16) __half g_W1h[(size_t)H * KEXP];       // 10.6 MB
__device__ float2 g_W2c[H * 9];
__device__ __align__(16) float2 g_part[(size_t)NROWS * NSLICES]; // 1.6 MB

// ---------------- helpers ----------------
__device__ __forceinline__ float siluf(float x) { return x / (1.0f + __expf(-x)); }
__device__ __forceinline__ float geluf(float x) {
    return 0.5f * x * (1.0f + erff(x * 0.70710678118654752f));
}

// v[0] = silu(x); v[1..8] = cubic B-spline bases (knots -2.2 + 0.4j). Branchless.
__device__ __forceinline__ void expand9(float x, float v[9]) {
    v[0] = siluf(x);
    float t  = (x + 2.2f) * 2.5f;
    float kf = floorf(t);
    int   k  = (int)kf;
    float u  = t - kf, u2 = u * u, u3 = u2 * u, om = 1.0f - u;
    bool ok = (k >= 0) && (k <= 10);
    float b0 = om * om * om * (1.0f / 6.0f);
    float b1 = (4.0f - 6.0f * u2 + 3.0f * u3) * (1.0f / 6.0f);
    float b2 = (1.0f + 3.0f * u + 3.0f * u2 - 3.0f * u3) * (1.0f / 6.0f);
    float b3 = u3 * (1.0f / 6.0f);
    int j0 = k - 3;
#pragma unroll
    for (int j = 0; j < 8; j++) {
        int d = j - j0;
        float bv = (d == 0) ? b0 : (d == 1) ? b1 : (d == 2) ? b2 : (d == 3) ? b3 : 0.0f;
        v[1 + j] = ok ? bv : 0.0f;
    }
}

__device__ __forceinline__ uint32_t smem_u32(const void* p) {
    uint32_t a;
    asm("{ .reg .u64 t; cvta.to.shared.u64 t, %1; cvt.u32.u64 %0, t; }" : "=r"(a) : "l"(p));
    return a;
}

__device__ __forceinline__ void cp16(uint32_t dst, const __half* gsrc) {
    asm volatile("cp.async.cg.shared.global [%0], [%1], 16;" :: "r"(dst), "l"(gsrc) : "memory");
}
#define CP_COMMIT() asm volatile("cp.async.commit_group;" ::: "memory")
#define CP_WAIT1()  asm volatile("cp.async.wait_group 1;" ::: "memory")
#define CP_WAIT0()  asm volatile("cp.async.wait_group 0;" ::: "memory")

__device__ __forceinline__ void ldm_x4(unsigned* d, uint32_t addr) {
    asm volatile("ldmatrix.sync.aligned.m8n8.x4.shared.b16 {%0,%1,%2,%3}, [%4];"
                 : "=r"(d[0]), "=r"(d[1]), "=r"(d[2]), "=r"(d[3]) : "r"(addr));
}

__device__ __forceinline__ void mma_f16(float* c, const unsigned* a,
                                        unsigned b0, unsigned b1) {
    asm volatile(
        "mma.sync.aligned.m16n8k16.row.col.f32.f16.f16.f32 "
        "{%0,%1,%2,%3}, {%4,%5,%6,%7}, {%8,%9}, {%0,%1,%2,%3};\n"
        : "+f"(c[0]), "+f"(c[1]), "+f"(c[2]), "+f"(c[3])
        : "r"(a[0]), "r"(a[1]), "r"(a[2]), "r"(a[3]), "r"(b0), "r"(b1));
}

// ---------------- merged weight prep (w1 rows + w2 in one launch) ----------
__global__ void prep_w(const float* __restrict__ bw1, const float* __restrict__ sw1,
                       const float* __restrict__ sc1, const float* __restrict__ bw2,
                       const float* __restrict__ sw2, const float* __restrict__ sc2) {
    __shared__ __half st[KEXP];                // 13824 B
    const int o = blockIdx.x;
    if (o < H) {                               // layer-1 weight row o
        for (int i = threadIdx.x; i < H; i += 256) {
            int idx = o * H + i;
            float s = sc1[idx];
            st[i * 9] = __float2half_rn(bw1[idx]);
#pragma unroll
            for (int j = 0; j < 8; j++)
                st[i * 9 + 1 + j] = __float2half_rn(sw1[(size_t)idx * 8 + j] * s);
        }
        __syncthreads();
        float4* dst = reinterpret_cast<float4*>(&g_W1h[(size_t)o * KEXP]);
        const float4* src = reinterpret_cast<const float4*>(st);
        for (int c = threadIdx.x; c < KEXP / 8; c += 256) dst[c] = src[c];
    } else {                                   // layer-2 combined weights
        for (int i = threadIdx.x; i < H; i += 256) {
            float s0 = sc2[i], s1 = sc2[H + i];
            g_W2c[i * 9] = make_float2(bw2[i], bw2[H + i]);
#pragma unroll
            for (int j = 0; j < 8; j++)
                g_W2c[i * 9 + 1 + j] = make_float2(sw2[(size_t)i * 8 + j] * s0,
                                                   sw2[(size_t)(H + i) * 8 + j] * s1);
        }
    }
}

// ---------------- one-time spline expansion (2 rows/block, coalesced) ------
__global__ void expand_a(const float* __restrict__ x) {
    __shared__ __half st[2 * KEXP];            // 27648 B
    const int half = threadIdx.x >> 8;         // 0/1 -> which row
    const int t    = threadIdx.x & 255;
    const int row  = blockIdx.x * 2 + half;
    __half* strow = st + half * KEXP;
    for (int i = t; i < H; i += 256) {
        float v[9];
        expand9(x[(size_t)row * H + i], v);
#pragma unroll
        for (int j = 0; j < 9; j++) strow[i * 9 + j] = __float2half_rn(v[j]);
    }
    __syncthreads();
    float4* dst = reinterpret_cast<float4*>(&g_Aexp[(size_t)(blockIdx.x * 2) * KEXP]);
    const float4* src = reinterpret_cast<const float4*>(st);
    for (int c = threadIdx.x; c < 2 * KEXP / 8; c += 512) dst[c] = src[c];
}

// ---------------- fused GEMM: layer1 + GELU + layer2-partials (r12 exact) --
__global__ void __launch_bounds__(256, 3) gemm_fused() {
    extern __shared__ __half sm[];
    const uint32_t sb = smem_u32(sm);
    const int tid = threadIdx.x, wid = tid >> 5, lane = tid & 31;
    const int g = lane >> 2, tg = lane & 3;
    const int wm = wid & 3, wn = wid >> 2;      // warp grid 4m x 2n, warp tile 32x32
    const int m0 = blockIdx.y * BM, n0 = blockIdx.x * BN;

    // ---- cp.async addressing: thread covers rows (tid>>3)+32r, 16B unit (tid&7) ----
    const int crow = tid >> 3, ccol = tid & 7;
    const int ckey = crow & 7;
    const __half* aBase = g_Aexp + (size_t)(m0 + crow) * KEXP + ccol * 8;
    const __half* bBase = g_W1h + (size_t)(n0 + crow) * KEXP + ccol * 8;
    const uint32_t aS = sb + crow * ROWB + (ccol ^ ckey) * 16;
    const uint32_t bS = aS + ASTGB;

    // ---- ldmatrix addressing: row base + precomputed swizzled 16B cols ----
    const int r8 = lane & 7, sel = lane >> 3;
    const uint32_t aRow = sb + (wm * 32 + ((sel & 1) << 3) + r8) * ROWB;
    const uint32_t bRow = sb + ASTGB + (wn * 32 + ((sel >> 1) << 3) + r8) * ROWB;
    uint32_t colA[4], colB[4];
#pragma unroll
    for (int ks = 0; ks < 4; ks++) {
        colA[ks] = ((((sel >> 1) + 2 * ks) ^ r8) << 4);
        colB[ks] = ((((sel & 1) + 2 * ks) ^ r8) << 4);
    }

    float c[2][4][4];
#pragma unroll
    for (int mt = 0; mt < 2; mt++)
#pragma unroll
        for (int nt = 0; nt < 4; nt++)
#pragma unroll
            for (int q = 0; q < 4; q++) c[mt][nt][q] = 0.0f;

    auto issue = [&](int kt) {
        const uint32_t st = (kt % NSTAGE) * STGB;
        const __half* ap = aBase + kt * BK;
#pragma unroll
        for (int r = 0; r < 4; r++)
            cp16(aS + st + r * (32 * ROWB), ap + (size_t)r * (32 * KEXP));
        const __half* bp = bBase + kt * BK;
#pragma unroll
        for (int r = 0; r < 2; r++)
            cp16(bS + st + r * (32 * ROWB), bp + (size_t)r * (32 * KEXP));
    };

    issue(0); CP_COMMIT();
    issue(1); CP_COMMIT();

    for (int kt = 0; kt < NKT; kt++) {
        if (kt < NKT - 2) { CP_WAIT1(); }   // stage kt complete, kt+1 in flight
        else              { CP_WAIT0(); }
        __syncthreads();                    // all warps done with iter kt-1 (slot (kt+2)%3 free)
        if (kt + 2 < NKT) { issue(kt + 2); CP_COMMIT(); }

        const uint32_t aR = aRow + (kt % NSTAGE) * STGB;
        const uint32_t bR = bRow + (kt % NSTAGE) * STGB;
#pragma unroll
        for (int ks = 0; ks < 4; ks++) {
            unsigned a[2][4], b[2][4];
#pragma unroll
            for (int mt = 0; mt < 2; mt++)
                ldm_x4(a[mt], aR + mt * (16 * ROWB) + colA[ks]);
#pragma unroll
            for (int np = 0; np < 2; np++)
                ldm_x4(b[np], bR + np * (16 * ROWB) + colB[ks]);
#pragma unroll
            for (int nt = 0; nt < 4; nt++) {
                unsigned b0 = b[nt >> 1][(nt & 1) * 2];
                unsigned b1 = b[nt >> 1][(nt & 1) * 2 + 1];
#pragma unroll
                for (int mt = 0; mt < 2; mt++)
                    mma_f16(c[mt][nt], a[mt], b0, b1);
            }
        }
    }

    // epilogue: gelu + spline-expand + layer-2 partial dot, then intra-CTA reduce
    __syncthreads();                        // mainloop smem reads complete before reuse
    float2* red = reinterpret_cast<float2*>(sm);   // [8][128] float2 = 8KB (aliases stage 0)
    const int sl8 = wn * 4 + tg;
#pragma unroll
    for (int mt = 0; mt < 2; mt++) {
#pragma unroll
        for (int hq = 0; hq < 2; hq++) {
            int rl = wm * 32 + mt * 16 + g + hq * 8;   // local row 0..127
            float p0 = 0.0f, p1 = 0.0f;
#pragma unroll
            for (int nt = 0; nt < 4; nt++) {
#pragma unroll
                for (int par = 0; par < 2; par++) {
                    float y = geluf(c[mt][nt][hq * 2 + par]);
                    int col = n0 + wn * 32 + nt * 8 + 2 * tg + par;
                    float v[9];
                    expand9(y, v);
                    const float2* w = &g_W2c[col * 9];
#pragma unroll
                    for (int j = 0; j < 9; j++) {
                        float2 wj = __ldg(&w[j]);
                        p0 = fmaf(v[j], wj.x, p0);
                        p1 = fmaf(v[j], wj.y, p1);
                    }
                }
            }
            red[sl8 * 128 + rl] = make_float2(p0, p1);
        }
    }
    __syncthreads();
    if (tid < 128) {
        float a = 0.0f, b = 0.0f;
#pragma unroll
        for (int s = 0; s < 8; s++) {
            float2 v = red[s * 128 + tid];
            a += v.x; b += v.y;
        }
        g_part[(size_t)(m0 + tid) * NSLICES + blockIdx.x] = make_float2(a, b);
    }
}

// ---------------- final reduce (12 float2 per row) ----------------
__global__ void reduce2(float* __restrict__ out) {
    int row = blockIdx.x * 256 + threadIdx.x;
    if (row >= NROWS) return;
    const float4* p = reinterpret_cast<const float4*>(&g_part[(size_t)row * NSLICES]);
    float a = 0.0f, b = 0.0f;
#pragma unroll
    for (int s = 0; s < NSLICES / 2; s++) {
        float4 v = p[s];
        a += v.x + v.z;
        b += v.y + v.w;
    }
    out[row * 2 + 0] = a;
    out[row * 2 + 1] = b;
}

// ---------------------------------------------------------------------------
extern "C" void kernel_launch(void* const* d_in, const int* in_sizes, int n_in,
                              void* d_out, int out_size) {
    const float* hidden = (const float*)d_in[0];
    const float* bw1 = (const float*)d_in[1];
    const float* sw1 = (const float*)d_in[2];
    const float* sc1 = (const float*)d_in[3];
    const float* bw2 = (const float*)d_in[4];
    const float* sw2 = (const float*)d_in[5];
    const float* sc2 = (const float*)d_in[6];
    float* out = (float*)d_out;

    cudaFuncSetAttribute(gemm_fused, cudaFuncAttributeMaxDynamicSharedMemorySize, SMEMSZ);

    prep_w<<<H + 1, 256>>>(bw1, sw1, sc1, bw2, sw2, sc2);
    expand_a<<<NROWS / 2, 512>>>(hidden);
    gemm_fused<<<dim3(NTILE, NROWS / BM), 256, SMEMSZ>>>();
    reduce2<<<NROWS / 256, 256>>>(out);
}